// round 3
// baseline (speedup 1.0000x reference)
#include <cuda_runtime.h>
#include <cstdint>
#include <cstddef>

// Problem constants (fixed by setup_inputs): B=2,H=16,L=4096,D=64
#define BH_N 32      // B*H
#define NB   64      // number of 64-wide blocks along L
#define DH   64      // head dim
#define TK   6       // top-k key blocks per query block = int(0.1*64)
#define SSTR 385     // smem stride for 64x384 S matrix (odd -> conflict-free)

// -------- device scratch (no allocations allowed) --------
__device__ float g_qb[BH_N*NB*DH];                       // block means of q
__device__ float g_kb[BH_N*NB*DH];                       // block means of k
__device__ int   g_lut[BH_N*NB*TK];                      // selected key blocks
__device__ float g_kv[(size_t)BH_N*NB*DH*DH];            // per-block phi(k)^T v  (33.5MB)
__device__ float g_z [BH_N*NB*DH];                       // per-block phi(k) sums
__device__ float g_kvtot[BH_N*DH*DH];                    // totals over blocks
__device__ float g_ztot [BH_N*DH];

// ---------------- kernel 1: block means ----------------
__global__ void k_means(const float* __restrict__ q, const float* __restrict__ k)
{
    int bh = blockIdx.x >> 6, blk = blockIdx.x & 63, d = threadIdx.x;
    size_t base = ((size_t)bh*4096 + (size_t)blk*64)*64 + d;
    float sq = 0.f, sk = 0.f;
#pragma unroll 8
    for (int r = 0; r < 64; r++) { sq += q[base + (size_t)r*64]; sk += k[base + (size_t)r*64]; }
    g_qb[(bh*64+blk)*64+d] = sq * (1.f/64.f);
    g_kb[(bh*64+blk)*64+d] = sk * (1.f/64.f);
}

// ---------------- kernel 2: block scores + top-6 ----------------
__global__ void k_topk()
{
    __shared__ float qrow[64], sc[64];
    __shared__ int   luts[TK];
    int bh = blockIdx.x >> 6, qi = blockIdx.x & 63, j = threadIdx.x;
    qrow[j] = g_qb[(bh*64+qi)*64+j];
    __syncthreads();
    const float* kbp = g_kb + (bh*64+j)*64;
    float s = 0.f;
#pragma unroll 8
    for (int d = 0; d < 64; d++) s += qrow[d] * kbp[d];
    sc[j] = s;                              // scale is positive -> ranking unchanged
    __syncthreads();
    if (j == 0) {
        for (int t = 0; t < TK; t++) {
            float best = -3.4e38f; int bi = 0;
            for (int i = 0; i < 64; i++) { float v = sc[i]; if (v > best) { best = v; bi = i; } }
            luts[t] = bi; sc[bi] = -3.4e38f;    // ties -> lowest index, matches jax top_k
        }
    }
    __syncthreads();
    if (j < TK) g_lut[(bh*64+qi)*TK + j] = luts[j];
}

// ---------------- kernel 3: per key block kv = phi(k)^T v, z = sum phi(k) ----------------
__global__ __launch_bounds__(256) void k_kv(const float* __restrict__ kg, const float* __restrict__ vg)
{
    __shared__ float ck[64*65];
    __shared__ float vs[64*65];
    int bh = blockIdx.x >> 6, kb = blockIdx.x & 63, tid = threadIdx.x;
    size_t base = ((size_t)bh*4096 + (size_t)kb*64)*64;
    for (int i = tid; i < 4096; i += 256) {
        ck[(i>>6)*65 + (i&63)] = kg[base + i];
        vs[(i>>6)*65 + (i&63)] = vg[base + i];
    }
    __syncthreads();
    // softmax rows of ck over D (4 threads per row)
    {
        int row = tid >> 2, sub = tid & 3;
        float mx = -3.4e38f;
#pragma unroll
        for (int kk = 0; kk < 16; kk++) mx = fmaxf(mx, ck[row*65 + sub + 4*kk]);
        mx = fmaxf(mx, __shfl_xor_sync(0xffffffffu, mx, 1));
        mx = fmaxf(mx, __shfl_xor_sync(0xffffffffu, mx, 2));
        float e[16]; float sum = 0.f;
#pragma unroll
        for (int kk = 0; kk < 16; kk++) { e[kk] = __expf(ck[row*65 + sub + 4*kk] - mx); sum += e[kk]; }
        sum += __shfl_xor_sync(0xffffffffu, sum, 1);
        sum += __shfl_xor_sync(0xffffffffu, sum, 2);
        float inv = 1.f / sum;
#pragma unroll
        for (int kk = 0; kk < 16; kk++) ck[row*65 + sub + 4*kk] = e[kk] * inv;
    }
    __syncthreads();
    // kv[d][e] = sum_m ck[m][d] * vs[m][e]
    int tx = tid & 15, ty = tid >> 4;
    float acc[4][4] = {};
#pragma unroll 8
    for (int m = 0; m < 64; m++) {
        float a[4], b[4];
#pragma unroll
        for (int i = 0; i < 4; i++) a[i] = ck[m*65 + ty + 16*i];
#pragma unroll
        for (int j = 0; j < 4; j++) b[j] = vs[m*65 + tx + 16*j];
#pragma unroll
        for (int i = 0; i < 4; i++)
#pragma unroll
            for (int j = 0; j < 4; j++) acc[i][j] += a[i] * b[j];
    }
    float* kvo = g_kv + (size_t)(bh*64+kb)*4096;
#pragma unroll
    for (int i = 0; i < 4; i++)
#pragma unroll
        for (int j = 0; j < 4; j++) kvo[(ty+16*i)*64 + tx + 16*j] = acc[i][j];
    if (tid < 64) {
        float zz = 0.f;
#pragma unroll 8
        for (int m = 0; m < 64; m++) zz += ck[m*65 + tid];
        g_z[(bh*64+kb)*64 + tid] = zz;
    }
}

// ---------------- kernel 3b: totals over key blocks ----------------
__global__ void k_tot()
{
    int bh = blockIdx.x >> 3, part = blockIdx.x & 7, tid = threadIdx.x;
    for (int idx = part*512 + tid; idx < part*512 + 512; idx += 256) {
        const float* p = g_kv + (size_t)bh*64*4096 + idx;
        float s = 0.f;
#pragma unroll 8
        for (int kb = 0; kb < 64; kb++) s += p[(size_t)kb*4096];
        g_kvtot[bh*4096 + idx] = s;
    }
    if (part == 0 && tid < 64) {
        const float* p = g_z + bh*64*64 + tid;
        float s = 0.f;
#pragma unroll 8
        for (int kb = 0; kb < 64; kb++) s += p[kb*64];
        g_ztot[bh*64 + tid] = s;
    }
}

// ---------------- kernel 4: fused sparse attn + linear complement + projection ----------------
// smem: S (64x385) | qs (64x65, Q -> c_q -> o_l) | tile (64x65, K/V/W staging) | zns/den/bl
#define SMEM_MAIN ((64*SSTR + 2*64*65 + 192) * sizeof(float))

__global__ __launch_bounds__(256, 1) void k_main(
    const float* __restrict__ q, const float* __restrict__ k, const float* __restrict__ v,
    const float* __restrict__ Wl, const float* __restrict__ bl, float* __restrict__ out)
{
    extern __shared__ float sm[];
    float* S    = sm;                 // 64*385
    float* qs   = S + 64*SSTR;        // 64*65
    float* tile = qs + 64*65;         // 64*65
    float* zns  = tile + 64*65;       // 64
    float* den  = zns + 64;           // 64
    float* blS  = den + 64;           // 64

    int bh = blockIdx.x >> 6, qi = blockIdx.x & 63;
    int tid = threadIdx.x;
    int tx = tid & 15, ty = tid >> 4;
    int row = tid >> 2, sub = tid & 3;

    int lut[TK];
    const int* lp = g_lut + (bh*64+qi)*TK;
#pragma unroll
    for (int t = 0; t < TK; t++) lut[t] = lp[t];

    const float* qp = q + ((size_t)bh*4096 + (size_t)qi*64)*64;
    for (int i = tid; i < 4096; i += 256) qs[(i>>6)*65 + (i&63)] = qp[i];
    if (tid < 64) blS[tid] = bl[tid];
    __syncthreads();

    // ---- S = Q @ Ksel^T * scale (scale = 1/8) ----
    for (int t = 0; t < TK; t++) {
        const float* kp = k + ((size_t)bh*4096 + (size_t)lut[t]*64)*64;
        for (int i = tid; i < 4096; i += 256) tile[(i>>6)*65 + (i&63)] = kp[i];
        __syncthreads();
        float acc[4][4] = {};
#pragma unroll 8
        for (int d = 0; d < 64; d++) {
            float a[4], b[4];
#pragma unroll
            for (int i = 0; i < 4; i++) a[i] = qs[(ty+16*i)*65 + d];
#pragma unroll
            for (int j = 0; j < 4; j++) b[j] = tile[(tx+16*j)*65 + d];
#pragma unroll
            for (int i = 0; i < 4; i++)
#pragma unroll
                for (int j = 0; j < 4; j++) acc[i][j] += a[i] * b[j];
        }
#pragma unroll
        for (int i = 0; i < 4; i++)
#pragma unroll
            for (int j = 0; j < 4; j++)
                S[(ty+16*i)*SSTR + t*64 + tx + 16*j] = acc[i][j] * 0.125f;
        __syncthreads();
    }

    // ---- softmax over the 384 selected keys (4 threads per row) ----
    {
        float mx = -3.4e38f;
        for (int m = sub; m < 384; m += 4) mx = fmaxf(mx, S[row*SSTR + m]);
        mx = fmaxf(mx, __shfl_xor_sync(0xffffffffu, mx, 1));
        mx = fmaxf(mx, __shfl_xor_sync(0xffffffffu, mx, 2));
        float sum = 0.f;
        for (int m = sub; m < 384; m += 4) { float e = __expf(S[row*SSTR + m] - mx); S[row*SSTR + m] = e; sum += e; }
        sum += __shfl_xor_sync(0xffffffffu, sum, 1);
        sum += __shfl_xor_sync(0xffffffffu, sum, 2);
        float inv = 1.f / sum;
        for (int m = sub; m < 384; m += 4) S[row*SSTR + m] *= inv;
    }
    // ---- c_q = softmax(q, axis=D) in place on qs ----
    {
        float mx = -3.4e38f;
#pragma unroll
        for (int kk = 0; kk < 16; kk++) mx = fmaxf(mx, qs[row*65 + sub + 4*kk]);
        mx = fmaxf(mx, __shfl_xor_sync(0xffffffffu, mx, 1));
        mx = fmaxf(mx, __shfl_xor_sync(0xffffffffu, mx, 2));
        float e[16]; float sum = 0.f;
#pragma unroll
        for (int kk = 0; kk < 16; kk++) { e[kk] = __expf(qs[row*65 + sub + 4*kk] - mx); sum += e[kk]; }
        sum += __shfl_xor_sync(0xffffffffu, sum, 1);
        sum += __shfl_xor_sync(0xffffffffu, sum, 2);
        float inv = 1.f / sum;
#pragma unroll
        for (int kk = 0; kk < 16; kk++) qs[row*65 + sub + 4*kk] = e[kk] * inv;
    }
    __syncthreads();

    // ---- O_s = P @ Vsel ----
    float accO[4][4] = {};
    for (int t = 0; t < TK; t++) {
        const float* vp = v + ((size_t)bh*4096 + (size_t)lut[t]*64)*64;
        for (int i = tid; i < 4096; i += 256) tile[(i>>6)*65 + (i&63)] = vp[i];
        __syncthreads();
#pragma unroll 8
        for (int m = 0; m < 64; m++) {
            float a[4], b[4];
#pragma unroll
            for (int i = 0; i < 4; i++) a[i] = S[(ty+16*i)*SSTR + t*64 + m];
#pragma unroll
            for (int j = 0; j < 4; j++) b[j] = tile[m*65 + tx + 16*j];
#pragma unroll
            for (int i = 0; i < 4; i++)
#pragma unroll
                for (int j = 0; j < 4; j++) accO[i][j] += a[i] * b[j];
        }
        __syncthreads();
    }

    // ---- complement kv/z (total - selected); kvns reuses S region with stride 65 ----
    {
        const float* kvt = g_kvtot + bh*4096;
        const float* kvb = g_kv + (size_t)bh*64*4096;
        for (int idx = tid; idx < 4096; idx += 256) {
            float s = kvt[idx];
#pragma unroll
            for (int t = 0; t < TK; t++) s -= kvb[(size_t)lut[t]*4096 + idx];
            S[(idx>>6)*65 + (idx&63)] = s;
        }
        if (tid < 64) {
            float s = g_ztot[bh*64 + tid];
#pragma unroll
            for (int t = 0; t < TK; t++) s -= g_z[(bh*64 + lut[t])*64 + tid];
            zns[tid] = s;
        }
    }
    __syncthreads();
    if (tid < 64) {
        float s = 0.f;
#pragma unroll 8
        for (int d = 0; d < 64; d++) s += qs[tid*65 + d] * zns[d];
        den[tid] = s;
    }
    __syncthreads();

    // ---- num = c_q @ kv_ns ----
    float accL[4][4] = {};
#pragma unroll 8
    for (int d = 0; d < 64; d++) {
        float a[4], b[4];
#pragma unroll
        for (int i = 0; i < 4; i++) a[i] = qs[(ty+16*i)*65 + d];
#pragma unroll
        for (int j = 0; j < 4; j++) b[j] = S[d*65 + tx + 16*j];
#pragma unroll
        for (int i = 0; i < 4; i++)
#pragma unroll
            for (int j = 0; j < 4; j++) accL[i][j] += a[i] * b[j];
    }
    float dn[4];
#pragma unroll
    for (int i = 0; i < 4; i++) dn[i] = 1.f / (den[ty+16*i] + 1e-6f);

    __syncthreads();   // all qs readers done before overwriting with o_l
    // o_l into qs; W_l into tile
#pragma unroll
    for (int i = 0; i < 4; i++)
#pragma unroll
        for (int j = 0; j < 4; j++) qs[(ty+16*i)*65 + tx + 16*j] = accL[i][j] * dn[i];
    for (int idx = tid; idx < 4096; idx += 256) tile[(idx>>6)*65 + (idx&63)] = Wl[idx];
    __syncthreads();

    // ---- out = O_s + o_l @ W_l^T + b_l ----
#pragma unroll 8
    for (int d = 0; d < 64; d++) {
        float a[4], b[4];
#pragma unroll
        for (int i = 0; i < 4; i++) a[i] = qs[(ty+16*i)*65 + d];
#pragma unroll
        for (int j = 0; j < 4; j++) b[j] = tile[(tx+16*j)*65 + d];
#pragma unroll
        for (int i = 0; i < 4; i++)
#pragma unroll
            for (int j = 0; j < 4; j++) accO[i][j] += a[i] * b[j];
    }
    float* op = out + ((size_t)bh*4096 + (size_t)qi*64)*64;
#pragma unroll
    for (int i = 0; i < 4; i++)
#pragma unroll
        for (int j = 0; j < 4; j++)
            op[(ty+16*i)*64 + tx + 16*j] = accO[i][j] + blS[tx+16*j];
}

// ---------------- launch ----------------
extern "C" void kernel_launch(void* const* d_in, const int* in_sizes, int n_in,
                              void* d_out, int out_size)
{
    const float* q  = (const float*)d_in[0];
    const float* k  = (const float*)d_in[1];
    const float* v  = (const float*)d_in[2];
    const float* Wl = (const float*)d_in[3];
    const float* bl = (const float*)d_in[4];
    float* out = (float*)d_out;

    cudaFuncSetAttribute(k_main, cudaFuncAttributeMaxDynamicSharedMemorySize, (int)SMEM_MAIN);

    k_means<<<BH_N*NB, 64>>>(q, k);
    k_topk <<<BH_N*NB, 64>>>();
    k_kv   <<<BH_N*NB, 256>>>(k, v);
    k_tot  <<<BH_N*8, 256>>>();
    k_main <<<BH_N*NB, 256, SMEM_MAIN>>>(q, k, v, Wl, bl, out);
}

// round 4
// speedup vs baseline: 1.3766x; 1.3766x over previous
#include <cuda_runtime.h>
#include <mma.h>
#include <cstdint>
#include <cstddef>

using namespace nvcuda;

// Problem constants (fixed by setup_inputs): B=2,H=16,L=4096,D=64
#define BH_N 32      // B*H
#define NB   64      // number of 64-wide blocks along L
#define DH   64      // head dim
#define TK   6       // top-k key blocks per query block = int(0.1*64)
#define SSTR 388     // smem stride for 64x384 S matrix (mult of 4 for wmma, 4-bank skew)
#define QSTR 68      // smem stride for 64x64 tiles

// -------- device scratch (no allocations allowed) --------
__device__ float g_qb[BH_N*NB*DH];
__device__ float g_kb[BH_N*NB*DH];
__device__ int   g_lut[BH_N*NB*TK];
__device__ float g_kv[(size_t)BH_N*NB*DH*DH];            // per-block phi(k)^T v
__device__ float g_z [BH_N*NB*DH];
__device__ float g_kvtot[BH_N*DH*DH];
__device__ float g_ztot [BH_N*DH];

typedef wmma::fragment<wmma::matrix_a,16,16,8,wmma::precision::tf32,wmma::row_major> FragA;
typedef wmma::fragment<wmma::matrix_a,16,16,8,wmma::precision::tf32,wmma::col_major> FragAc;
typedef wmma::fragment<wmma::matrix_b,16,16,8,wmma::precision::tf32,wmma::row_major> FragB;
typedef wmma::fragment<wmma::matrix_b,16,16,8,wmma::precision::tf32,wmma::col_major> FragBc;
typedef wmma::fragment<wmma::accumulator,16,16,8,float> FragC;

#define CVT_TF32(f) do { for (int _e = 0; _e < (f).num_elements; _e++) (f).x[_e] = wmma::__float_to_tf32((f).x[_e]); } while (0)

// ---------------- kernel 1: block means ----------------
__global__ void k_means(const float* __restrict__ q, const float* __restrict__ k)
{
    int bh = blockIdx.x >> 6, blk = blockIdx.x & 63, d = threadIdx.x;
    size_t base = ((size_t)bh*4096 + (size_t)blk*64)*64 + d;
    float sq = 0.f, sk = 0.f;
#pragma unroll 8
    for (int r = 0; r < 64; r++) { sq += q[base + (size_t)r*64]; sk += k[base + (size_t)r*64]; }
    g_qb[(bh*64+blk)*64+d] = sq * (1.f/64.f);
    g_kb[(bh*64+blk)*64+d] = sk * (1.f/64.f);
}

// ---------------- kernel 2: block scores + top-6 ----------------
__global__ void k_topk()
{
    __shared__ float qrow[64], sc[64];
    __shared__ int   luts[TK];
    int bh = blockIdx.x >> 6, qi = blockIdx.x & 63, j = threadIdx.x;
    qrow[j] = g_qb[(bh*64+qi)*64+j];
    __syncthreads();
    const float* kbp = g_kb + (bh*64+j)*64;
    float s = 0.f;
#pragma unroll 8
    for (int d = 0; d < 64; d++) s += qrow[d] * kbp[d];
    sc[j] = s;
    __syncthreads();
    if (j == 0) {
        for (int t = 0; t < TK; t++) {
            float best = -3.4e38f; int bi = 0;
            for (int i = 0; i < 64; i++) { float v = sc[i]; if (v > best) { best = v; bi = i; } }
            luts[t] = bi; sc[bi] = -3.4e38f;    // ties -> lowest index, matches jax top_k
        }
    }
    __syncthreads();
    if (j < TK) g_lut[(bh*64+qi)*TK + j] = luts[j];
}

// ---------------- kernel 3: per key block kv = phi(k)^T v, z = sum phi(k) ----------------
__global__ __launch_bounds__(256) void k_kv(const float* __restrict__ kg, const float* __restrict__ vg)
{
    __shared__ float ck[64*QSTR];
    int bh = blockIdx.x >> 6, kb = blockIdx.x & 63, tid = threadIdx.x;
    int wid = tid >> 5;
    size_t base = ((size_t)bh*4096 + (size_t)kb*64)*64;
    const float* vp = vg + base;
    for (int i = tid; i < 4096; i += 256)
        ck[(i>>6)*QSTR + (i&63)] = kg[base + i];
    __syncthreads();
    // softmax rows of ck over D (4 threads per row)
    {
        int row = tid >> 2, sub = tid & 3;
        float mx = -3.4e38f;
#pragma unroll
        for (int kk = 0; kk < 16; kk++) mx = fmaxf(mx, ck[row*QSTR + sub + 4*kk]);
        mx = fmaxf(mx, __shfl_xor_sync(0xffffffffu, mx, 1));
        mx = fmaxf(mx, __shfl_xor_sync(0xffffffffu, mx, 2));
        float e[16]; float sum = 0.f;
#pragma unroll
        for (int kk = 0; kk < 16; kk++) { e[kk] = __expf(ck[row*QSTR + sub + 4*kk] - mx); sum += e[kk]; }
        sum += __shfl_xor_sync(0xffffffffu, sum, 1);
        sum += __shfl_xor_sync(0xffffffffu, sum, 2);
        float inv = 1.f / sum;
#pragma unroll
        for (int kk = 0; kk < 16; kk++) ck[row*QSTR + sub + 4*kk] = e[kk] * inv;
    }
    __syncthreads();
    // kv[d][e] = sum_m ck[m][d] * vs[m][e]  via tf32 wmma (A = ck^T col_major)
    int r = wid >> 1, cpair = (wid & 1) * 2;
    FragC acc[2];
    wmma::fill_fragment(acc[0], 0.f);
    wmma::fill_fragment(acc[1], 0.f);
#pragma unroll
    for (int kk = 0; kk < 8; kk++) {
        FragAc a;
        wmma::load_matrix_sync(a, ck + r*16 + kk*8*QSTR, QSTR);
        CVT_TF32(a);
#pragma unroll
        for (int c = 0; c < 2; c++) {
            FragB b;
            wmma::load_matrix_sync(b, vp + kk*8*64 + (cpair+c)*16, 64);
            CVT_TF32(b);
            wmma::mma_sync(acc[c], a, b, acc[c]);
        }
    }
    float* kvo = g_kv + (size_t)(bh*64+kb)*4096;
#pragma unroll
    for (int c = 0; c < 2; c++)
        wmma::store_matrix_sync(kvo + r*16*64 + (cpair+c)*16, acc[c], 64, wmma::mem_row_major);
    if (tid < 64) {
        float zz = 0.f;
#pragma unroll 8
        for (int m = 0; m < 64; m++) zz += ck[m*QSTR + tid];
        g_z[(bh*64+kb)*64 + tid] = zz;
    }
}

// ---------------- kernel 3b: totals over key blocks ----------------
__global__ void k_tot()
{
    int bh = blockIdx.x >> 4, part = blockIdx.x & 15, tid = threadIdx.x;
    int idx = part*256 + tid;
    {
        const float* p = g_kv + (size_t)bh*64*4096 + idx;
        float s = 0.f;
#pragma unroll 8
        for (int kb = 0; kb < 64; kb++) s += p[(size_t)kb*4096];
        g_kvtot[bh*4096 + idx] = s;
    }
    if (part == 0 && tid < 64) {
        const float* p = g_z + bh*64*64 + tid;
        float s = 0.f;
#pragma unroll 8
        for (int kb = 0; kb < 64; kb++) s += p[kb*64];
        g_ztot[bh*64 + tid] = s;
    }
}

// ---------------- kernel 4: fused sparse attn + linear complement + projection ----------------
// smem: S (64 x SSTR) | qs (64 x QSTR) | zns | den
// dead P region reuse: kvns at S[0..] (stride 68), o_l at S+8192, out staging at S+16384
#define SMEM_MAIN ((64*SSTR + 64*QSTR + 128) * sizeof(float))

__global__ __launch_bounds__(256, 1) void k_main(
    const float* __restrict__ q, const float* __restrict__ k, const float* __restrict__ v,
    const float* __restrict__ Wl, const float* __restrict__ bl, float* __restrict__ out)
{
    extern __shared__ float sm[];
    float* S    = sm;                  // 64*SSTR
    float* qs   = S + 64*SSTR;         // 64*QSTR
    float* zns  = qs + 64*QSTR;        // 64
    float* den  = zns + 64;            // 64
    float* olS  = S + 8192;            // 64*QSTR (o_l staging)
    float* outS = S + 16384;           // 64*QSTR (output staging)

    int bh = blockIdx.x >> 6, qi = blockIdx.x & 63;
    int tid = threadIdx.x, wid = tid >> 5;
    int r = wid >> 1;                  // row tile 0..3 (rows r*16..r*16+15)
    int cpair = (wid & 1) * 2;         // col tiles cpair, cpair+1 (of 4 per 64 cols)
    int row = tid >> 2, sub = tid & 3;

    int lut[TK];
    const int* lp = g_lut + (bh*64+qi)*TK;
#pragma unroll
    for (int t = 0; t < TK; t++) lut[t] = lp[t];

    const float* qp = q + ((size_t)bh*4096 + (size_t)qi*64)*64;
    for (int i = tid; i < 4096; i += 256) qs[(i>>6)*QSTR + (i&63)] = qp[i];

    // hoist Q A-fragments (rows r*16, all 8 k-slices) straight from global
    FragA aQ[8];
#pragma unroll
    for (int kk = 0; kk < 8; kk++) {
        wmma::load_matrix_sync(aQ[kk], qp + r*16*64 + kk*8, 64);
        CVT_TF32(aQ[kk]);
    }

    // ---- S = Q @ Ksel^T * scale (scale = 1/8); K fragments direct from global ----
    for (int t = 0; t < TK; t++) {
        const float* kp = k + ((size_t)bh*4096 + (size_t)lut[t]*64)*64;
        FragC acc[2];
        wmma::fill_fragment(acc[0], 0.f);
        wmma::fill_fragment(acc[1], 0.f);
#pragma unroll
        for (int kk = 0; kk < 8; kk++) {
#pragma unroll
            for (int c = 0; c < 2; c++) {
                FragBc b;
                wmma::load_matrix_sync(b, kp + (cpair+c)*16*64 + kk*8, 64);
                CVT_TF32(b);
                wmma::mma_sync(acc[c], aQ[kk], b, acc[c]);
            }
        }
#pragma unroll
        for (int c = 0; c < 2; c++) {
            for (int e = 0; e < acc[c].num_elements; e++) acc[c].x[e] *= 0.125f;
            wmma::store_matrix_sync(S + r*16*SSTR + t*64 + (cpair+c)*16, acc[c], SSTR, wmma::mem_row_major);
        }
    }
    __syncthreads();

    // ---- softmax over the 384 selected keys (4 threads per row) ----
    {
        float mx = -3.4e38f;
        for (int m = sub; m < 384; m += 4) mx = fmaxf(mx, S[row*SSTR + m]);
        mx = fmaxf(mx, __shfl_xor_sync(0xffffffffu, mx, 1));
        mx = fmaxf(mx, __shfl_xor_sync(0xffffffffu, mx, 2));
        float sum = 0.f;
        for (int m = sub; m < 384; m += 4) { float e = __expf(S[row*SSTR + m] - mx); S[row*SSTR + m] = e; sum += e; }
        sum += __shfl_xor_sync(0xffffffffu, sum, 1);
        sum += __shfl_xor_sync(0xffffffffu, sum, 2);
        float inv = 1.f / sum;
        for (int m = sub; m < 384; m += 4) S[row*SSTR + m] *= inv;
    }
    // ---- c_q = softmax(q, axis=D) in place on qs ----
    {
        float mx = -3.4e38f;
#pragma unroll
        for (int kk = 0; kk < 16; kk++) mx = fmaxf(mx, qs[row*QSTR + sub + 4*kk]);
        mx = fmaxf(mx, __shfl_xor_sync(0xffffffffu, mx, 1));
        mx = fmaxf(mx, __shfl_xor_sync(0xffffffffu, mx, 2));
        float e[16]; float sum = 0.f;
#pragma unroll
        for (int kk = 0; kk < 16; kk++) { e[kk] = __expf(qs[row*QSTR + sub + 4*kk] - mx); sum += e[kk]; }
        sum += __shfl_xor_sync(0xffffffffu, sum, 1);
        sum += __shfl_xor_sync(0xffffffffu, sum, 2);
        float inv = 1.f / sum;
#pragma unroll
        for (int kk = 0; kk < 16; kk++) qs[row*QSTR + sub + 4*kk] = e[kk] * inv;
    }
    __syncthreads();

    // ---- O_s = P @ Vsel (V fragments direct from global) ----
    FragC accO[2];
    wmma::fill_fragment(accO[0], 0.f);
    wmma::fill_fragment(accO[1], 0.f);
    for (int t = 0; t < TK; t++) {
        const float* vp = v + ((size_t)bh*4096 + (size_t)lut[t]*64)*64;
#pragma unroll
        for (int kk = 0; kk < 8; kk++) {
            FragA aP;
            wmma::load_matrix_sync(aP, S + r*16*SSTR + t*64 + kk*8, SSTR);
            CVT_TF32(aP);
#pragma unroll
            for (int c = 0; c < 2; c++) {
                FragB b;
                wmma::load_matrix_sync(b, vp + kk*8*64 + (cpair+c)*16, 64);
                CVT_TF32(b);
                wmma::mma_sync(accO[c], aP, b, accO[c]);
            }
        }
    }
    __syncthreads();   // all reads of S(P) done before overwriting with kv_ns

    // ---- complement kv/z (total - selected); kvns into S[0..] with stride 68 ----
    {
        const float* kvt = g_kvtot + bh*4096;
        const float* kvb = g_kv + (size_t)bh*64*4096;
        for (int idx = tid; idx < 4096; idx += 256) {
            float s = kvt[idx];
#pragma unroll
            for (int t = 0; t < TK; t++) s -= kvb[(size_t)lut[t]*4096 + idx];
            S[(idx>>6)*QSTR + (idx&63)] = s;
        }
        if (tid < 64) {
            float s = g_ztot[bh*64 + tid];
#pragma unroll
            for (int t = 0; t < TK; t++) s -= g_z[(bh*64 + lut[t])*64 + tid];
            zns[tid] = s;
        }
    }
    __syncthreads();
    if (tid < 64) {
        float s = 0.f;
#pragma unroll 8
        for (int d = 0; d < 64; d++) s += qs[tid*QSTR + d] * zns[d];
        den[tid] = s;
    }

    // ---- num = c_q @ kv_ns ----
    {
        FragC accL[2];
        wmma::fill_fragment(accL[0], 0.f);
        wmma::fill_fragment(accL[1], 0.f);
#pragma unroll
        for (int kk = 0; kk < 8; kk++) {
            FragA a;
            wmma::load_matrix_sync(a, qs + r*16*QSTR + kk*8, QSTR);
            CVT_TF32(a);
#pragma unroll
            for (int c = 0; c < 2; c++) {
                FragB b;
                wmma::load_matrix_sync(b, S + kk*8*QSTR + (cpair+c)*16, QSTR);
                CVT_TF32(b);
                wmma::mma_sync(accL[c], a, b, accL[c]);
            }
        }
#pragma unroll
        for (int c = 0; c < 2; c++)
            wmma::store_matrix_sync(olS + r*16*QSTR + (cpair+c)*16, accL[c], QSTR, wmma::mem_row_major);
    }
    __syncthreads();   // den ready + olS stores visible

    // ---- o_l = num / (den + 1e-6) in place on olS ----
    for (int i = tid; i < 4096; i += 256) {
        int rr = i >> 6, c = i & 63;
        olS[rr*QSTR + c] *= 1.f / (den[rr] + 1e-6f);
    }
    __syncthreads();

    // ---- out = O_s + o_l @ W_l^T + b_l  (W fragments direct from global) ----
#pragma unroll
    for (int kk = 0; kk < 8; kk++) {
        FragA a;
        wmma::load_matrix_sync(a, olS + r*16*QSTR + kk*8, QSTR);
        CVT_TF32(a);
#pragma unroll
        for (int c = 0; c < 2; c++) {
            FragBc b;
            wmma::load_matrix_sync(b, Wl + (cpair+c)*16*64 + kk*8, 64);
            CVT_TF32(b);
            wmma::mma_sync(accO[c], a, b, accO[c]);
        }
    }
#pragma unroll
    for (int c = 0; c < 2; c++)
        wmma::store_matrix_sync(outS + r*16*QSTR + (cpair+c)*16, accO[c], QSTR, wmma::mem_row_major);
    __syncthreads();

    float* op = out + ((size_t)bh*4096 + (size_t)qi*64)*64;
    for (int i = tid; i < 4096; i += 256)
        op[i] = outS[(i>>6)*QSTR + (i&63)] + bl[i&63];
}

// ---------------- launch ----------------
extern "C" void kernel_launch(void* const* d_in, const int* in_sizes, int n_in,
                              void* d_out, int out_size)
{
    const float* q  = (const float*)d_in[0];
    const float* k  = (const float*)d_in[1];
    const float* v  = (const float*)d_in[2];
    const float* Wl = (const float*)d_in[3];
    const float* bl = (const float*)d_in[4];
    float* out = (float*)d_out;

    cudaFuncSetAttribute(k_main, cudaFuncAttributeMaxDynamicSharedMemorySize, (int)SMEM_MAIN);

    k_means<<<BH_N*NB, 64>>>(q, k);
    k_topk <<<BH_N*NB, 64>>>();
    k_kv   <<<BH_N*NB, 256>>>(k, v);
    k_tot  <<<BH_N*16, 256>>>();
    k_main <<<BH_N*NB, 256, SMEM_MAIN>>>(q, k, v, Wl, bl, out);
}

// round 5
// speedup vs baseline: 1.7072x; 1.2402x over previous
#include <cuda_runtime.h>
#include <mma.h>
#include <cstdint>
#include <cstddef>

using namespace nvcuda;

// Problem constants (fixed by setup_inputs): B=2,H=16,L=4096,D=64
#define BH_N 32      // B*H
#define NB   64      // number of 64-wide blocks along L
#define DH   64      // head dim
#define TK   6       // top-k key blocks per query block = int(0.1*64)
#define SSTR 388     // smem stride for 64x384 S matrix (mult of 4 for wmma, 4-bank skew)
#define QSTR 68      // smem stride for 64x64 tiles

// -------- device scratch (no allocations allowed) --------
__device__ float g_qb[BH_N*NB*DH];
__device__ float g_kb[BH_N*NB*DH];
__device__ int   g_lut[BH_N*NB*TK];
__device__ float g_kv[(size_t)BH_N*NB*DH*DH];            // per-block phi(k)^T v
__device__ float g_z [BH_N*NB*DH];
__device__ float g_kvtot[BH_N*DH*DH];
__device__ float g_ztot [BH_N*DH];

typedef wmma::fragment<wmma::matrix_a,16,16,8,wmma::precision::tf32,wmma::row_major> FragA;
typedef wmma::fragment<wmma::matrix_a,16,16,8,wmma::precision::tf32,wmma::col_major> FragAc;
typedef wmma::fragment<wmma::matrix_b,16,16,8,wmma::precision::tf32,wmma::row_major> FragB;
typedef wmma::fragment<wmma::matrix_b,16,16,8,wmma::precision::tf32,wmma::col_major> FragBc;
typedef wmma::fragment<wmma::accumulator,16,16,8,float> FragC;

#define CVT_TF32(f) do { for (int _e = 0; _e < (f).num_elements; _e++) (f).x[_e] = wmma::__float_to_tf32((f).x[_e]); } while (0)

// ---- cp.async helpers ----
__device__ __forceinline__ void cpa16(float* dst_smem, const float* src_gmem) {
    uint32_t d = (uint32_t)__cvta_generic_to_shared(dst_smem);
    asm volatile("cp.async.cg.shared.global [%0], [%1], 16;\n" :: "r"(d), "l"(src_gmem));
}
#define CP_COMMIT() asm volatile("cp.async.commit_group;\n" ::: "memory")
#define CP_WAIT(n)  asm volatile("cp.async.wait_group %0;\n" :: "n"(n) : "memory")

// stage a 64x64 fp32 tile (gmem row stride 64) into smem with row stride QSTR
template<int NT>
__device__ __forceinline__ void stage_tile(float* buf, const float* src, int tid) {
#pragma unroll
    for (int j = 0; j < 1024/NT; j++) {
        int id = tid + NT*j;
        int row = id >> 4, seg = id & 15;
        cpa16(buf + row*QSTR + seg*4, src + row*64 + seg*4);
    }
}

// ---------------- kernel 1: block means ----------------
__global__ void k_means(const float* __restrict__ q, const float* __restrict__ k)
{
    int bh = blockIdx.x >> 6, blk = blockIdx.x & 63, d = threadIdx.x;
    size_t base = ((size_t)bh*4096 + (size_t)blk*64)*64 + d;
    float sq = 0.f, sk = 0.f;
#pragma unroll 8
    for (int r = 0; r < 64; r++) { sq += q[base + (size_t)r*64]; sk += k[base + (size_t)r*64]; }
    g_qb[(bh*64+blk)*64+d] = sq * (1.f/64.f);
    g_kb[(bh*64+blk)*64+d] = sk * (1.f/64.f);
}

// ---------------- kernel 2: block scores + top-6 ----------------
__global__ void k_topk()
{
    __shared__ float qrow[64], sc[64];
    __shared__ int   luts[TK];
    int bh = blockIdx.x >> 6, qi = blockIdx.x & 63, j = threadIdx.x;
    qrow[j] = g_qb[(bh*64+qi)*64+j];
    __syncthreads();
    const float* kbp = g_kb + (bh*64+j)*64;
    float s = 0.f;
#pragma unroll 8
    for (int d = 0; d < 64; d++) s += qrow[d] * kbp[d];
    sc[j] = s;
    __syncthreads();
    if (j == 0) {
        for (int t = 0; t < TK; t++) {
            float best = -3.4e38f; int bi = 0;
            for (int i = 0; i < 64; i++) { float v = sc[i]; if (v > best) { best = v; bi = i; } }
            luts[t] = bi; sc[bi] = -3.4e38f;    // ties -> lowest index, matches jax top_k
        }
    }
    __syncthreads();
    if (j < TK) g_lut[(bh*64+qi)*TK + j] = luts[j];
}

// ---------------- kernel 3: per key block kv = phi(k)^T v, z = sum phi(k) ----------------
__global__ __launch_bounds__(256) void k_kv(const float* __restrict__ kg, const float* __restrict__ vg)
{
    __shared__ float ck[64*QSTR];
    __shared__ float vs[64*QSTR];
    int bh = blockIdx.x >> 6, kb = blockIdx.x & 63, tid = threadIdx.x;
    int wid = tid >> 5;
    size_t base = ((size_t)bh*4096 + (size_t)kb*64)*64;
    stage_tile<256>(vs, vg + base, tid);
    CP_COMMIT();
    for (int i = tid; i < 4096; i += 256)
        ck[(i>>6)*QSTR + (i&63)] = kg[base + i];
    __syncthreads();
    // softmax rows of ck over D (4 threads per row)
    {
        int row = tid >> 2, sub = tid & 3;
        float mx = -3.4e38f;
#pragma unroll
        for (int kk = 0; kk < 16; kk++) mx = fmaxf(mx, ck[row*QSTR + sub + 4*kk]);
        mx = fmaxf(mx, __shfl_xor_sync(0xffffffffu, mx, 1));
        mx = fmaxf(mx, __shfl_xor_sync(0xffffffffu, mx, 2));
        float e[16]; float sum = 0.f;
#pragma unroll
        for (int kk = 0; kk < 16; kk++) { e[kk] = __expf(ck[row*QSTR + sub + 4*kk] - mx); sum += e[kk]; }
        sum += __shfl_xor_sync(0xffffffffu, sum, 1);
        sum += __shfl_xor_sync(0xffffffffu, sum, 2);
        float inv = 1.f / sum;
#pragma unroll
        for (int kk = 0; kk < 16; kk++) ck[row*QSTR + sub + 4*kk] = e[kk] * inv;
    }
    CP_WAIT(0);
    __syncthreads();
    // kv[d][e] = sum_m ck[m][d] * vs[m][e]  via tf32 wmma (A = ck^T col_major)
    int r = wid >> 1, cpair = (wid & 1) * 2;
    FragC acc[2];
    wmma::fill_fragment(acc[0], 0.f);
    wmma::fill_fragment(acc[1], 0.f);
#pragma unroll
    for (int kk = 0; kk < 8; kk++) {
        FragAc a;
        wmma::load_matrix_sync(a, ck + r*16 + kk*8*QSTR, QSTR);
        CVT_TF32(a);
#pragma unroll
        for (int c = 0; c < 2; c++) {
            FragB b;
            wmma::load_matrix_sync(b, vs + kk*8*QSTR + (cpair+c)*16, QSTR);
            CVT_TF32(b);
            wmma::mma_sync(acc[c], a, b, acc[c]);
        }
    }
    float* kvo = g_kv + (size_t)(bh*64+kb)*4096;
#pragma unroll
    for (int c = 0; c < 2; c++)
        wmma::store_matrix_sync(kvo + r*16*64 + (cpair+c)*16, acc[c], 64, wmma::mem_row_major);
    if (tid < 64) {
        float zz = 0.f;
#pragma unroll 8
        for (int m = 0; m < 64; m++) zz += ck[m*QSTR + tid];
        g_z[(bh*64+kb)*64 + tid] = zz;
    }
}

// ---------------- kernel 3b: totals over key blocks ----------------
__global__ void k_tot()
{
    int bh = blockIdx.x >> 4, part = blockIdx.x & 15, tid = threadIdx.x;
    int idx = part*256 + tid;
    {
        const float* p = g_kv + (size_t)bh*64*4096 + idx;
        float s = 0.f;
#pragma unroll 8
        for (int kb = 0; kb < 64; kb++) s += p[(size_t)kb*4096];
        g_kvtot[bh*4096 + idx] = s;
    }
    if (part == 0 && tid < 64) {
        const float* p = g_z + bh*64*64 + tid;
        float s = 0.f;
#pragma unroll 8
        for (int kb = 0; kb < 64; kb++) s += p[kb*64];
        g_ztot[bh*64 + tid] = s;
    }
}

// ---------------- kernel 4: fused sparse attn + linear complement + projection ----------------
// smem: S (64 x SSTR) | qs (64 x QSTR) | buf0 | buf1 (K/V/W staging, cp.async) | zns | den
// dead P region reuse: kvns at S[0..] (stride 68), o_l at S+8192, out staging at S+16384
#define SMEM_MAIN ((64*SSTR + 3*64*QSTR + 128) * sizeof(float))

__global__ __launch_bounds__(512, 1) void k_main(
    const float* __restrict__ q, const float* __restrict__ k, const float* __restrict__ v,
    const float* __restrict__ Wl, const float* __restrict__ bl, float* __restrict__ out)
{
    extern __shared__ float sm[];
    float* S    = sm;                  // 64*SSTR
    float* qs   = S + 64*SSTR;         // 64*QSTR
    float* buf0 = qs + 64*QSTR;        // 64*QSTR staging
    float* buf1 = buf0 + 64*QSTR;      // 64*QSTR staging
    float* zns  = buf1 + 64*QSTR;      // 64
    float* den  = zns + 64;            // 64
    float* olS  = S + 8192;            // 64*QSTR (o_l staging)
    float* outS = S + 16384;           // 64*QSTR (output staging)
    float* bufs[2] = {buf0, buf1};

    int bh = blockIdx.x >> 6, qi = blockIdx.x & 63;
    int tid = threadIdx.x, wid = tid >> 5;
    int r  = wid >> 2;                 // row tile 0..3
    int cc = wid & 3;                  // col tile 0..3
    int row = tid >> 3, sub = tid & 7; // softmax: 8 threads per row

    int lut[TK];
    const int* lp = g_lut + (bh*64+qi)*TK;
#pragma unroll
    for (int t = 0; t < TK; t++) lut[t] = lp[t];

    const float* qp = q + ((size_t)bh*4096 + (size_t)qi*64)*64;
    const float* kbase = k + (size_t)bh*4096*64;
    const float* vbase = v + (size_t)bh*4096*64;

    // prefetch K[lut[0]] while staging Q
    stage_tile<512>(bufs[0], kbase + (size_t)lut[0]*4096, tid);
    CP_COMMIT();
    for (int i = tid; i < 4096; i += 512) qs[(i>>6)*QSTR + (i&63)] = qp[i];
    __syncthreads();

    // hoist Q A-fragments (rows r*16, all 8 k-slices) from staged smem
    FragA aQ[8];
#pragma unroll
    for (int kk = 0; kk < 8; kk++) {
        wmma::load_matrix_sync(aQ[kk], qs + r*16*QSTR + kk*8, QSTR);
        CVT_TF32(aQ[kk]);
    }

    // ---- S = Q @ Ksel^T * scale (scale = 1/8); K staged via cp.async double buffer ----
    for (int t = 0; t < TK; t++) {
        if (t+1 < TK) {
            stage_tile<512>(bufs[(t+1)&1], kbase + (size_t)lut[t+1]*4096, tid);
            CP_COMMIT();
            CP_WAIT(1);
        } else {
            CP_WAIT(0);
        }
        __syncthreads();
        const float* kb = bufs[t&1];
        FragC acc;
        wmma::fill_fragment(acc, 0.f);
#pragma unroll
        for (int kk = 0; kk < 8; kk++) {
            FragBc b;
            wmma::load_matrix_sync(b, kb + cc*16*QSTR + kk*8, QSTR);
            CVT_TF32(b);
            wmma::mma_sync(acc, aQ[kk], b, acc);
        }
        for (int e = 0; e < acc.num_elements; e++) acc.x[e] *= 0.125f;
        wmma::store_matrix_sync(S + r*16*SSTR + t*64 + cc*16, acc, SSTR, wmma::mem_row_major);
        __syncthreads();
    }

    // prefetch V[lut[0]] into buf0 (buf0's last compute was t=4, already done)
    stage_tile<512>(bufs[0], vbase + (size_t)lut[0]*4096, tid);
    CP_COMMIT();

    // ---- softmax over the 384 selected keys (8 threads per row) ----
    {
        float mx = -3.4e38f;
        for (int m = sub; m < 384; m += 8) mx = fmaxf(mx, S[row*SSTR + m]);
        mx = fmaxf(mx, __shfl_xor_sync(0xffffffffu, mx, 1));
        mx = fmaxf(mx, __shfl_xor_sync(0xffffffffu, mx, 2));
        mx = fmaxf(mx, __shfl_xor_sync(0xffffffffu, mx, 4));
        float sum = 0.f;
        for (int m = sub; m < 384; m += 8) { float e = __expf(S[row*SSTR + m] - mx); S[row*SSTR + m] = e; sum += e; }
        sum += __shfl_xor_sync(0xffffffffu, sum, 1);
        sum += __shfl_xor_sync(0xffffffffu, sum, 2);
        sum += __shfl_xor_sync(0xffffffffu, sum, 4);
        float inv = 1.f / sum;
        for (int m = sub; m < 384; m += 8) S[row*SSTR + m] *= inv;
    }
    // ---- c_q = softmax(q, axis=D) in place on qs ----
    {
        float mx = -3.4e38f;
#pragma unroll
        for (int kk = 0; kk < 8; kk++) mx = fmaxf(mx, qs[row*QSTR + sub + 8*kk]);
        mx = fmaxf(mx, __shfl_xor_sync(0xffffffffu, mx, 1));
        mx = fmaxf(mx, __shfl_xor_sync(0xffffffffu, mx, 2));
        mx = fmaxf(mx, __shfl_xor_sync(0xffffffffu, mx, 4));
        float e[8]; float sum = 0.f;
#pragma unroll
        for (int kk = 0; kk < 8; kk++) { e[kk] = __expf(qs[row*QSTR + sub + 8*kk] - mx); sum += e[kk]; }
        sum += __shfl_xor_sync(0xffffffffu, sum, 1);
        sum += __shfl_xor_sync(0xffffffffu, sum, 2);
        sum += __shfl_xor_sync(0xffffffffu, sum, 4);
        float inv = 1.f / sum;
#pragma unroll
        for (int kk = 0; kk < 8; kk++) qs[row*QSTR + sub + 8*kk] = e[kk] * inv;
    }
    __syncthreads();

    // ---- O_s = P @ Vsel (V staged via cp.async double buffer) ----
    FragC accO;
    wmma::fill_fragment(accO, 0.f);
    for (int t = 0; t < TK; t++) {
        if (t+1 < TK) {
            stage_tile<512>(bufs[(t+1)&1], vbase + (size_t)lut[t+1]*4096, tid);
            CP_COMMIT();
            CP_WAIT(1);
        } else {
            CP_WAIT(0);
        }
        __syncthreads();
        const float* vb = bufs[t&1];
#pragma unroll
        for (int kk = 0; kk < 8; kk++) {
            FragA aP;
            wmma::load_matrix_sync(aP, S + r*16*SSTR + t*64 + kk*8, SSTR);
            CVT_TF32(aP);
            FragB b;
            wmma::load_matrix_sync(b, vb + kk*8*QSTR + cc*16, QSTR);
            CVT_TF32(b);
            wmma::mma_sync(accO, aP, b, accO);
        }
        __syncthreads();
    }

    // prefetch W_l into buf0 (hidden behind the complement's global reads)
    stage_tile<512>(bufs[0], Wl, tid);
    CP_COMMIT();

    // ---- complement kv/z (total - selected); kvns into S[0..] with stride 68 ----
    {
        const float* kvt = g_kvtot + bh*4096;
        const float* kvb = g_kv + (size_t)bh*64*4096;
        for (int idx = tid; idx < 4096; idx += 512) {
            float s = kvt[idx];
#pragma unroll
            for (int t = 0; t < TK; t++) s -= kvb[(size_t)lut[t]*4096 + idx];
            S[(idx>>6)*QSTR + (idx&63)] = s;
        }
        if (tid < 64) {
            float s = g_ztot[bh*64 + tid];
#pragma unroll
            for (int t = 0; t < TK; t++) s -= g_z[(bh*64 + lut[t])*64 + tid];
            zns[tid] = s;
        }
    }
    __syncthreads();
    if (tid < 64) {
        float s = 0.f;
#pragma unroll 8
        for (int d = 0; d < 64; d++) s += qs[tid*QSTR + d] * zns[d];
        den[tid] = s;
    }

    // ---- num = c_q @ kv_ns ----
    {
        FragC accL;
        wmma::fill_fragment(accL, 0.f);
#pragma unroll
        for (int kk = 0; kk < 8; kk++) {
            FragA a;
            wmma::load_matrix_sync(a, qs + r*16*QSTR + kk*8, QSTR);
            CVT_TF32(a);
            FragB b;
            wmma::load_matrix_sync(b, S + kk*8*QSTR + cc*16, QSTR);
            CVT_TF32(b);
            wmma::mma_sync(accL, a, b, accL);
        }
        wmma::store_matrix_sync(olS + r*16*QSTR + cc*16, accL, QSTR, wmma::mem_row_major);
    }
    __syncthreads();   // den ready + olS stores visible

    // ---- o_l = num / (den + 1e-6) in place on olS ----
    for (int i = tid; i < 4096; i += 512) {
        int rr = i >> 6, c = i & 63;
        olS[rr*QSTR + c] *= 1.f / (den[rr] + 1e-6f);
    }
    CP_WAIT(0);        // W_l staged
    __syncthreads();

    // ---- out = O_s + o_l @ W_l^T + b_l  (W from staged smem, col_major) ----
#pragma unroll
    for (int kk = 0; kk < 8; kk++) {
        FragA a;
        wmma::load_matrix_sync(a, olS + r*16*QSTR + kk*8, QSTR);
        CVT_TF32(a);
        FragBc b;
        wmma::load_matrix_sync(b, bufs[0] + cc*16*QSTR + kk*8, QSTR);
        CVT_TF32(b);
        wmma::mma_sync(accO, a, b, accO);
    }
    wmma::store_matrix_sync(outS + r*16*QSTR + cc*16, accO, QSTR, wmma::mem_row_major);
    __syncthreads();

    float* op = out + ((size_t)bh*4096 + (size_t)qi*64)*64;
    for (int i = tid; i < 4096; i += 512)
        op[i] = outS[(i>>6)*QSTR + (i&63)] + bl[i&63];
}

// ---------------- launch ----------------
extern "C" void kernel_launch(void* const* d_in, const int* in_sizes, int n_in,
                              void* d_out, int out_size)
{
    const float* q  = (const float*)d_in[0];
    const float* k  = (const float*)d_in[1];
    const float* v  = (const float*)d_in[2];
    const float* Wl = (const float*)d_in[3];
    const float* bl = (const float*)d_in[4];
    float* out = (float*)d_out;

    cudaFuncSetAttribute(k_main, cudaFuncAttributeMaxDynamicSharedMemorySize, (int)SMEM_MAIN);

    k_means<<<BH_N*NB, 64>>>(q, k);
    k_topk <<<BH_N*NB, 64>>>();
    k_kv   <<<BH_N*NB, 256>>>(k, v);
    k_tot  <<<BH_N*16, 256>>>();
    k_main <<<BH_N*NB, 512, SMEM_MAIN>>>(q, k, v, Wl, bl, out);
}

// round 6
// speedup vs baseline: 2.0511x; 1.2014x over previous
#include <cuda_runtime.h>
#include <mma.h>
#include <cstdint>
#include <cstddef>

using namespace nvcuda;

// Problem constants (fixed by setup_inputs): B=2,H=16,L=4096,D=64
#define BH_N 32      // B*H
#define NB   64      // blocks along L
#define DH   64      // head dim
#define TK   6       // top-k key blocks per query block
#define QSTR 68      // smem stride for 64x64 tiles (mult of 4 for wmma, 4-bank skew)

// -------- device scratch --------
__device__ float g_qb[BH_N*NB*DH];
__device__ float g_kb[BH_N*NB*DH];
__device__ int   g_lut[BH_N*NB*TK];
__device__ float g_kv[(size_t)BH_N*NB*DH*DH];
__device__ float g_z [BH_N*NB*DH];
__device__ float g_kvtot[BH_N*DH*DH];
__device__ float g_ztot [BH_N*DH];

typedef wmma::fragment<wmma::matrix_a,16,16,8,wmma::precision::tf32,wmma::row_major> FragA;
typedef wmma::fragment<wmma::matrix_a,16,16,8,wmma::precision::tf32,wmma::col_major> FragAc;
typedef wmma::fragment<wmma::matrix_b,16,16,8,wmma::precision::tf32,wmma::row_major> FragB;
typedef wmma::fragment<wmma::matrix_b,16,16,8,wmma::precision::tf32,wmma::col_major> FragBc;
typedef wmma::fragment<wmma::accumulator,16,16,8,float> FragC;

#define CVT_TF32(f) do { for (int _e = 0; _e < (f).num_elements; _e++) (f).x[_e] = wmma::__float_to_tf32((f).x[_e]); } while (0)

__device__ __forceinline__ void cpa16(float* dst_smem, const float* src_gmem) {
    uint32_t d = (uint32_t)__cvta_generic_to_shared(dst_smem);
    asm volatile("cp.async.cg.shared.global [%0], [%1], 16;\n" :: "r"(d), "l"(src_gmem));
}
#define CP_COMMIT() asm volatile("cp.async.commit_group;\n" ::: "memory")
#define CP_WAIT(n)  asm volatile("cp.async.wait_group %0;\n" :: "n"(n) : "memory")

// stage a 64x64 fp32 tile (gmem row stride 64) into smem with row stride QSTR
template<int NT>
__device__ __forceinline__ void stage_tile(float* buf, const float* src, int tid) {
#pragma unroll
    for (int j = 0; j < 1024/NT; j++) {
        int id = tid + NT*j;
        int row = id >> 4, seg = id & 15;
        cpa16(buf + row*QSTR + seg*4, src + row*64 + seg*4);
    }
}

// ---------------- kernel 1: block means ----------------
__global__ void k_means(const float* __restrict__ q, const float* __restrict__ k)
{
    int bh = blockIdx.x >> 6, blk = blockIdx.x & 63, d = threadIdx.x;
    size_t base = ((size_t)bh*4096 + (size_t)blk*64)*64 + d;
    float sq = 0.f, sk = 0.f;
#pragma unroll 8
    for (int r = 0; r < 64; r++) { sq += q[base + (size_t)r*64]; sk += k[base + (size_t)r*64]; }
    g_qb[(bh*64+blk)*64+d] = sq * (1.f/64.f);
    g_kb[(bh*64+blk)*64+d] = sk * (1.f/64.f);
}

// ---------------- kernel 2: block scores + top-6 ----------------
__global__ void k_topk()
{
    __shared__ float qrow[64], sc[64];
    __shared__ int   luts[TK];
    int bh = blockIdx.x >> 6, qi = blockIdx.x & 63, j = threadIdx.x;
    qrow[j] = g_qb[(bh*64+qi)*64+j];
    __syncthreads();
    const float* kbp = g_kb + (bh*64+j)*64;
    float s = 0.f;
#pragma unroll 8
    for (int d = 0; d < 64; d++) s += qrow[d] * kbp[d];
    sc[j] = s;
    __syncthreads();
    if (j == 0) {
        for (int t = 0; t < TK; t++) {
            float best = -3.4e38f; int bi = 0;
            for (int i = 0; i < 64; i++) { float v = sc[i]; if (v > best) { best = v; bi = i; } }
            luts[t] = bi; sc[bi] = -3.4e38f;    // ties -> lowest index, matches jax top_k
        }
    }
    __syncthreads();
    if (j < TK) g_lut[(bh*64+qi)*TK + j] = luts[j];
}

// ---------------- kernel 3: per key block kv = phi(k)^T v ----------------
__global__ __launch_bounds__(256) void k_kv(const float* __restrict__ kg, const float* __restrict__ vg)
{
    __shared__ float ck[64*QSTR];
    __shared__ float vs[64*QSTR];
    int bh = blockIdx.x >> 6, kb = blockIdx.x & 63, tid = threadIdx.x;
    int wid = tid >> 5;
    size_t base = ((size_t)bh*4096 + (size_t)kb*64)*64;
    stage_tile<256>(vs, vg + base, tid);
    CP_COMMIT();
    for (int i = tid; i < 4096; i += 256)
        ck[(i>>6)*QSTR + (i&63)] = kg[base + i];
    __syncthreads();
    {
        int row = tid >> 2, sub = tid & 3;
        float mx = -3.4e38f;
#pragma unroll
        for (int kk = 0; kk < 16; kk++) mx = fmaxf(mx, ck[row*QSTR + sub + 4*kk]);
        mx = fmaxf(mx, __shfl_xor_sync(0xffffffffu, mx, 1));
        mx = fmaxf(mx, __shfl_xor_sync(0xffffffffu, mx, 2));
        float e[16]; float sum = 0.f;
#pragma unroll
        for (int kk = 0; kk < 16; kk++) { e[kk] = __expf(ck[row*QSTR + sub + 4*kk] - mx); sum += e[kk]; }
        sum += __shfl_xor_sync(0xffffffffu, sum, 1);
        sum += __shfl_xor_sync(0xffffffffu, sum, 2);
        float inv = 1.f / sum;
#pragma unroll
        for (int kk = 0; kk < 16; kk++) ck[row*QSTR + sub + 4*kk] = e[kk] * inv;
    }
    CP_WAIT(0);
    __syncthreads();
    int r = wid >> 1, cpair = (wid & 1) * 2;
    FragC acc[2];
    wmma::fill_fragment(acc[0], 0.f);
    wmma::fill_fragment(acc[1], 0.f);
#pragma unroll
    for (int kk = 0; kk < 8; kk++) {
        FragAc a;
        wmma::load_matrix_sync(a, ck + r*16 + kk*8*QSTR, QSTR);
        CVT_TF32(a);
#pragma unroll
        for (int c = 0; c < 2; c++) {
            FragB b;
            wmma::load_matrix_sync(b, vs + kk*8*QSTR + (cpair+c)*16, QSTR);
            CVT_TF32(b);
            wmma::mma_sync(acc[c], a, b, acc[c]);
        }
    }
    float* kvo = g_kv + (size_t)(bh*64+kb)*4096;
#pragma unroll
    for (int c = 0; c < 2; c++)
        wmma::store_matrix_sync(kvo + r*16*64 + (cpair+c)*16, acc[c], 64, wmma::mem_row_major);
    if (tid < 64) {
        float zz = 0.f;
#pragma unroll 8
        for (int m = 0; m < 64; m++) zz += ck[m*QSTR + tid];
        g_z[(bh*64+kb)*64 + tid] = zz;
    }
}

// ---------------- kernel 3b: totals over key blocks ----------------
__global__ void k_tot()
{
    int bh = blockIdx.x >> 4, part = blockIdx.x & 15, tid = threadIdx.x;
    int idx = part*256 + tid;
    {
        const float* p = g_kv + (size_t)bh*64*4096 + idx;
        float s = 0.f;
#pragma unroll 8
        for (int kb = 0; kb < 64; kb++) s += p[(size_t)kb*4096];
        g_kvtot[bh*4096 + idx] = s;
    }
    if (part == 0 && tid < 64) {
        const float* p = g_z + bh*64*64 + tid;
        float s = 0.f;
#pragma unroll 8
        for (int kb = 0; kb < 64; kb++) s += p[kb*64];
        g_ztot[bh*64 + tid] = s;
    }
}

// ---------------- kernel 4: flash-style fused kernel, 2 CTAs/SM ----------------
// smem tiles (all 64 x QSTR): qs | st | Ob | buf0 | buf1 | buf2  + row arrays
#define SMEM_MAIN ((6*64*QSTR + 5*64) * sizeof(float))

__global__ __launch_bounds__(512, 2) void k_main(
    const float* __restrict__ q, const float* __restrict__ k, const float* __restrict__ v,
    const float* __restrict__ Wl, const float* __restrict__ bl, float* __restrict__ out)
{
    extern __shared__ float sm[];
    float* qs   = sm;                 // Q -> c_q
    float* st   = qs  + 64*QSTR;      // S tile -> P tile -> PV tile -> kv_ns
    float* Ob   = st  + 64*QSTR;      // O accumulator (unnormalized)
    float* buf0 = Ob  + 64*QSTR;
    float* buf1 = buf0 + 64*QSTR;
    float* buf2 = buf1 + 64*QSTR;
    float* rowm = buf2 + 64*QSTR;     // 64  running max
    float* rowl = rowm + 64;          // 64  running sum
    float* rowf = rowl + 64;          // 64  rescale factor / inv-l
    float* zns  = rowf + 64;          // 64
    float* den  = zns + 64;           // 64
    float* const bufs[3] = {buf0, buf1, buf2};

    int bh = blockIdx.x >> 6, qi = blockIdx.x & 63;
    int tid = threadIdx.x, wid = tid >> 5;
    int r  = wid >> 2;                 // warp row tile 0..3
    int cc = wid & 3;                  // warp col tile 0..3
    int row = tid >> 3, sub = tid & 7; // 8 threads per row for row passes

    int lut[TK];
    const int* lp = g_lut + (bh*64+qi)*TK;
#pragma unroll
    for (int t = 0; t < TK; t++) lut[t] = lp[t];

    const float* qp = q + ((size_t)bh*4096 + (size_t)qi*64)*64;
    const float* kbase = k + (size_t)bh*4096*64;
    const float* vbase = v + (size_t)bh*4096*64;

    // prologue: G0 = Q + K0, G1 = V0, G2 = K1; zero O, init row state
    stage_tile<512>(qs, qp, tid);
    stage_tile<512>(bufs[0], kbase + (size_t)lut[0]*4096, tid);
    CP_COMMIT();
    stage_tile<512>(bufs[1], vbase + (size_t)lut[0]*4096, tid);
    CP_COMMIT();
    stage_tile<512>(bufs[2], kbase + (size_t)lut[1]*4096, tid);
    CP_COMMIT();
    if (tid < 64) { rowm[tid] = -3.4e38f; rowl[tid] = 0.f; }
    for (int i = tid; i < 64*QSTR; i += 512) Ob[i] = 0.f;

    // flash loop over the TK selected key blocks
    // load i: K_t = group 2t, V_t = group 2t+1; buffer = load_index % 3
#pragma unroll
    for (int t = 0; t < TK; t++) {
        if (t < 5) { CP_WAIT(2); } else { CP_WAIT(0); }
        __syncthreads();                         // K_t visible; prev O-update done
        const float* kb = bufs[(2*t) % 3];
        FragC s;
        wmma::fill_fragment(s, 0.f);
#pragma unroll
        for (int kk = 0; kk < 8; kk++) {
            FragA a;
            wmma::load_matrix_sync(a, qs + r*16*QSTR + kk*8, QSTR);
            CVT_TF32(a);
            FragBc b;
            wmma::load_matrix_sync(b, kb + cc*16*QSTR + kk*8, QSTR);
            CVT_TF32(b);
            wmma::mma_sync(s, a, b, s);
        }
        for (int e = 0; e < s.num_elements; e++) s.x[e] *= 0.125f;
        wmma::store_matrix_sync(st + r*16*QSTR + cc*16, s, QSTR, wmma::mem_row_major);
        __syncthreads();                         // S visible; kb fully read by all
        if (t < 5) {                             // V_{t+1} into kb's buffer
            stage_tile<512>(bufs[(2*t) % 3], vbase + (size_t)lut[t+1]*4096, tid);
            CP_COMMIT();
        }
        // ---- online softmax row pass (8 threads/row) ----
        {
            float mx = -3.4e38f;
#pragma unroll
            for (int kk = 0; kk < 8; kk++) mx = fmaxf(mx, st[row*QSTR + sub + 8*kk]);
            mx = fmaxf(mx, __shfl_xor_sync(0xffffffffu, mx, 1));
            mx = fmaxf(mx, __shfl_xor_sync(0xffffffffu, mx, 2));
            mx = fmaxf(mx, __shfl_xor_sync(0xffffffffu, mx, 4));
            float m_old = rowm[row];
            float m_new = fmaxf(m_old, mx);
            float sum = 0.f;
#pragma unroll
            for (int kk = 0; kk < 8; kk++) {
                float e = __expf(st[row*QSTR + sub + 8*kk] - m_new);
                st[row*QSTR + sub + 8*kk] = e;
                sum += e;
            }
            sum += __shfl_xor_sync(0xffffffffu, sum, 1);
            sum += __shfl_xor_sync(0xffffffffu, sum, 2);
            sum += __shfl_xor_sync(0xffffffffu, sum, 4);
            if (sub == 0) {
                float f = __expf(m_old - m_new);
                rowf[row] = f;
                rowl[row] = rowl[row] * f + sum;
                rowm[row] = m_new;
            }
        }
        if (t < 5) { CP_WAIT(2); } else { CP_WAIT(0); }
        __syncthreads();                         // P + rowf + V_t visible
        const float* vb = bufs[(2*t+1) % 3];
        FragC pv;
        wmma::fill_fragment(pv, 0.f);
#pragma unroll
        for (int kk = 0; kk < 8; kk++) {
            FragA aP;
            wmma::load_matrix_sync(aP, st + r*16*QSTR + kk*8, QSTR);
            CVT_TF32(aP);
            FragB bv;
            wmma::load_matrix_sync(bv, vb + kk*8*QSTR + cc*16, QSTR);
            CVT_TF32(bv);
            wmma::mma_sync(pv, aP, bv, pv);
        }
        __syncthreads();                         // all P reads done
        wmma::store_matrix_sync(st + r*16*QSTR + cc*16, pv, QSTR, wmma::mem_row_major);
        __syncthreads();                         // PV visible; vb fully read
        if (t < 4) {                             // K_{t+2} into vb's buffer
            stage_tile<512>(bufs[(2*t+1) % 3], kbase + (size_t)lut[t+2]*4096, tid);
            CP_COMMIT();
        }
        // O = O * f + PV  (scalar, 8 elems/thread)
#pragma unroll
        for (int j = 0; j < 8; j++) {
            int i = tid + 512*j;
            int rr = i >> 6, col = i & 63;
            float fct = rowf[rr];
            Ob[rr*QSTR + col] = Ob[rr*QSTR + col] * fct + st[rr*QSTR + col];
        }
    }
    __syncthreads();                             // O-updates done

    // stage W_l into buf0 (free) while doing scalar work
    stage_tile<512>(buf0, Wl, tid);
    CP_COMMIT();

    // ---- c_q = softmax(Q, axis=D) in place on qs (8 threads/row) ----
    {
        float mx = -3.4e38f;
#pragma unroll
        for (int kk = 0; kk < 8; kk++) mx = fmaxf(mx, qs[row*QSTR + sub + 8*kk]);
        mx = fmaxf(mx, __shfl_xor_sync(0xffffffffu, mx, 1));
        mx = fmaxf(mx, __shfl_xor_sync(0xffffffffu, mx, 2));
        mx = fmaxf(mx, __shfl_xor_sync(0xffffffffu, mx, 4));
        float e[8]; float sum = 0.f;
#pragma unroll
        for (int kk = 0; kk < 8; kk++) { e[kk] = __expf(qs[row*QSTR + sub + 8*kk] - mx); sum += e[kk]; }
        sum += __shfl_xor_sync(0xffffffffu, sum, 1);
        sum += __shfl_xor_sync(0xffffffffu, sum, 2);
        sum += __shfl_xor_sync(0xffffffffu, sum, 4);
        float inv = 1.f / sum;
#pragma unroll
        for (int kk = 0; kk < 8; kk++) qs[row*QSTR + sub + 8*kk] = e[kk] * inv;
    }
    // ---- complement kv_ns into st; zns ----
    {
        const float* kvt = g_kvtot + bh*4096;
        const float* kvb = g_kv + (size_t)bh*64*4096;
        for (int idx = tid; idx < 4096; idx += 512) {
            float s = kvt[idx];
#pragma unroll
            for (int t = 0; t < TK; t++) s -= kvb[(size_t)lut[t]*4096 + idx];
            st[(idx>>6)*QSTR + (idx&63)] = s;
        }
        if (tid < 64) {
            float s = g_ztot[bh*64 + tid];
#pragma unroll
            for (int t = 0; t < TK; t++) s -= g_z[(bh*64 + lut[t])*64 + tid];
            zns[tid] = s;
        }
    }
    __syncthreads();
    if (tid < 64) {
        float s = 0.f;
#pragma unroll 8
        for (int d = 0; d < 64; d++) s += qs[tid*QSTR + d] * zns[d];
        den[tid] = s;
        rowf[tid] = 1.f / rowl[tid];             // reuse rowf as 1/l
    }
    // ---- num = c_q @ kv_ns -> buf1 ----
    {
        FragC nm;
        wmma::fill_fragment(nm, 0.f);
#pragma unroll
        for (int kk = 0; kk < 8; kk++) {
            FragA a;
            wmma::load_matrix_sync(a, qs + r*16*QSTR + kk*8, QSTR);
            CVT_TF32(a);
            FragB b;
            wmma::load_matrix_sync(b, st + kk*8*QSTR + cc*16, QSTR);
            CVT_TF32(b);
            wmma::mma_sync(nm, a, b, nm);
        }
        wmma::store_matrix_sync(buf1 + r*16*QSTR + cc*16, nm, QSTR, wmma::mem_row_major);
    }
    __syncthreads();                             // den + buf1 + rowf visible
    // ---- o_l = num / (den + 1e-6) in place on buf1 ----
    for (int idx = tid; idx < 4096; idx += 512) {
        int rr = idx >> 6, col = idx & 63;
        buf1[rr*QSTR + col] *= 1.f / (den[rr] + 1e-6f);
    }
    CP_WAIT(0);                                  // W_l staged
    __syncthreads();
    // ---- proj = o_l @ W_l^T -> buf2 ----
    {
        FragC pj;
        wmma::fill_fragment(pj, 0.f);
#pragma unroll
        for (int kk = 0; kk < 8; kk++) {
            FragA a;
            wmma::load_matrix_sync(a, buf1 + r*16*QSTR + kk*8, QSTR);
            CVT_TF32(a);
            FragBc b;
            wmma::load_matrix_sync(b, buf0 + cc*16*QSTR + kk*8, QSTR);
            CVT_TF32(b);
            wmma::mma_sync(pj, a, b, pj);
        }
        wmma::store_matrix_sync(buf2 + r*16*QSTR + cc*16, pj, QSTR, wmma::mem_row_major);
    }
    __syncthreads();

    // ---- out = O/l + proj + b_l ----
    float* op = out + ((size_t)bh*4096 + (size_t)qi*64)*64;
#pragma unroll
    for (int j = 0; j < 8; j++) {
        int i = tid + 512*j;
        int rr = i >> 6, col = i & 63;
        op[i] = Ob[rr*QSTR + col] * rowf[rr] + buf2[rr*QSTR + col] + bl[col];
    }
}

// ---------------- launch ----------------
extern "C" void kernel_launch(void* const* d_in, const int* in_sizes, int n_in,
                              void* d_out, int out_size)
{
    const float* q  = (const float*)d_in[0];
    const float* k  = (const float*)d_in[1];
    const float* v  = (const float*)d_in[2];
    const float* Wl = (const float*)d_in[3];
    const float* bl = (const float*)d_in[4];
    float* out = (float*)d_out;

    cudaFuncSetAttribute(k_main, cudaFuncAttributeMaxDynamicSharedMemorySize, (int)SMEM_MAIN);

    k_means<<<BH_N*NB, 64>>>(q, k);
    k_topk <<<BH_N*NB, 64>>>();
    k_kv   <<<BH_N*NB, 256>>>(k, v);
    k_tot  <<<BH_N*16, 256>>>();
    k_main <<<BH_N*NB, 512, SMEM_MAIN>>>(q, k, v, Wl, bl, out);
}